// round 15
// baseline (speedup 1.0000x reference)
#include <cuda_runtime.h>
#include <math.h>

#define B_ 2
#define S_ 512
#define D_ 768
#define H_ 12
#define DH_ 64
#define EA_ 4
#define EF_ 8
#define DFF_ 3072
#define K_ 2
#define NT_ 1024
#define CAP_ 160
#define BSD_ 786432

// ---------------- scratch ----------------------------------------------------
__device__ float g_xn1[NT_*D_];
__device__ float g_q[NT_*D_];
__device__ float g_kv[NT_*D_];
__device__ int   g_idx[NT_*H_];
__device__ int   g_headcnt[H_*EA_];
__device__ float g_vproj[H_*NT_*DH_];
__device__ float g_p[(size_t)B_*H_*S_*S_];
__device__ float g_x1[NT_*D_];
__device__ float g_xn2[NT_*D_];
__device__ float g_glr[NT_*64];
__device__ float g_glf[NT_*64];
__device__ int   g_topidx[NT_*K_];
__device__ float g_rawp[NT_*K_];
__device__ float g_w[NT_*K_];
__device__ int   g_keep[NT_*K_];
__device__ int   g_slot[EF_*CAP_];
__device__ int   g_ecnt[EF_];
__device__ float g_eimp[EF_];
__device__ float g_hmid[EF_*CAP_*DFF_];

#define g_attn g_xn1   // liveness-disjoint alias

// ---------------- mma helpers -----------------------------------------------
__device__ __forceinline__ unsigned f2tf(float f) {
    unsigned u; asm("cvt.rna.tf32.f32 %0, %1;" : "=r"(u) : "f"(f)); return u;
}
__device__ __forceinline__ void mma8(float* c, const unsigned* a, const unsigned* b) {
    asm("mma.sync.aligned.m16n8k8.row.col.f32.tf32.tf32.f32 "
        "{%0,%1,%2,%3},{%4,%5,%6,%7},{%8,%9},{%0,%1,%2,%3};"
        : "+f"(c[0]), "+f"(c[1]), "+f"(c[2]), "+f"(c[3])
        : "r"(a[0]), "r"(a[1]), "r"(a[2]), "r"(a[3]), "r"(b[0]), "r"(b[1]));
}
__device__ __forceinline__ void st4(unsigned* dst, float4 v) {
    uint4 u; u.x = f2tf(v.x); u.y = f2tf(v.y); u.z = f2tf(v.z); u.w = f2tf(v.w);
    *(uint4*)dst = u;
}
__device__ __forceinline__ float warp_sum(float v) {
    #pragma unroll
    for (int o = 16; o; o >>= 1) v += __shfl_xor_sync(0xffffffffu, v, o);
    return v;
}
__device__ __forceinline__ float warp_max(float v) {
    #pragma unroll
    for (int o = 16; o; o >>= 1) v = fmaxf(v, __shfl_xor_sync(0xffffffffu, v, o));
    return v;
}

// ---------------- init -------------------------------------------------------
__global__ void init_kernel() {
    int t = blockIdx.x*blockDim.x + threadIdx.x;
    if (t < H_*EA_) g_headcnt[t] = 0;
    if (t < EF_)    g_eimp[t] = 0.f;
    if (t < NT_*64) { g_glr[t] = 0.f; g_glf[t] = 0.f; }
}

// ---------------- layernorm --------------------------------------------------
__global__ void ln_kernel(const float* __restrict__ xext,
                          const float* __restrict__ g,
                          const float* __restrict__ b, int which) {
    int wid = threadIdx.x >> 5, lane = threadIdx.x & 31;
    int row = blockIdx.x*8 + wid;
    const float* xr = (which == 0 ? xext : g_x1) + row*D_;
    float* outr = (which == 0 ? g_xn1 : g_xn2) + row*D_;
    float v[24];
    float s = 0.f;
    #pragma unroll
    for (int i = 0; i < 24; i++) { v[i] = xr[lane + 32*i]; s += v[i]; }
    float mu = warp_sum(s) * (1.f/D_);
    float var = 0.f;
    #pragma unroll
    for (int i = 0; i < 24; i++) { float d = v[i]-mu; var += d*d; }
    float inv = rsqrtf(warp_sum(var) * (1.f/D_) + 1e-5f);
    #pragma unroll
    for (int i = 0; i < 24; i++) {
        int c = lane + 32*i;
        outr[c] = (v[i]-mu)*inv*g[c] + b[c];
    }
}

// ---------------- small-N fp32 GEMM: 64x64 tiles -----------------------------
__global__ void smalln_gemm(const float* __restrict__ Bsrc, int ncols, int which) {
    const float* A = which ? g_xn2 : g_xn1;
    float* Cpad    = which ? g_glf : g_glr;
    __shared__ float As[64][17];
    __shared__ float Bs[16][68];
    int tid = threadIdx.x;
    int row0 = blockIdx.x*64;
    int kbase = blockIdx.y*64;
    int tx = tid & 63;
    int ty = tid >> 6;
    float acc[16];
    #pragma unroll
    for (int i = 0; i < 16; i++) acc[i] = 0.f;
    for (int k0 = kbase; k0 < kbase + 64; k0 += 16) {
        int ar = tid >> 2, ac4 = (tid & 3)*4;
        float4 va = *(const float4*)&A[(row0+ar)*D_ + k0 + ac4];
        As[ar][ac4]   = va.x;
        As[ar][ac4+1] = va.y;
        As[ar][ac4+2] = va.z;
        As[ar][ac4+3] = va.w;
        int bk = tid >> 4, bc4 = (tid & 15)*4;
        #pragma unroll
        for (int j = 0; j < 4; j++) {
            int c = bc4 + j;
            Bs[bk][c] = (c < ncols) ? Bsrc[(size_t)(k0+bk)*ncols + c] : 0.f;
        }
        __syncthreads();
        #pragma unroll
        for (int k = 0; k < 16; k++) {
            float bv = Bs[k][tx];
            #pragma unroll
            for (int i = 0; i < 16; i++) acc[i] += As[ty*16 + i][k]*bv;
        }
        __syncthreads();
    }
    #pragma unroll
    for (int i = 0; i < 16; i++)
        atomicAdd(&Cpad[(row0 + ty*16 + i)*64 + tx], acc[i]);
}

// ---------------- router argmax ----------------------------------------------
__global__ void argmax_router() {
    int id = blockIdx.x*256 + threadIdx.x;
    if (id >= NT_*H_) return;
    int n = id / H_, h = id % H_;
    const float* gv = &g_glr[n*64 + h*EA_];
    float best = gv[0]; int bi = 0;
    #pragma unroll
    for (int e = 1; e < EA_; e++) { float v = gv[e]; if (v > best) { best = v; bi = e; } }
    g_idx[n*H_ + h] = bi;
    atomicAdd(&g_headcnt[h*EA_ + bi], 1);
}

// ---------------- V projection -----------------------------------------------
__global__ void vproj_kernel(const float* __restrict__ Wv) {
    int h = blockIdx.y;
    int tl = threadIdx.x >> 6;
    int d  = threadIdx.x & 63;
    int n = blockIdx.x*4 + tl;
    __shared__ float xs[4][DH_];
    xs[tl][d] = g_xn1[n*D_ + h*DH_ + d];
    __syncthreads();
    int e = g_idx[n*H_ + h];
    const float* W = Wv + ((size_t)(h*EA_+e))*DH_*DH_;
    float acc = 0.f;
    #pragma unroll 16
    for (int k = 0; k < DH_; k++) acc += xs[tl][k]*W[k*DH_ + d];
    g_vproj[(h*NT_ + n)*DH_ + d] = acc;
}

// ---------------- O projection + residual ------------------------------------
__global__ void oproj_kernel(const float* __restrict__ x, const float* __restrict__ Wo,
                             float* __restrict__ out) {
    int h = blockIdx.y;
    int tl = threadIdx.x >> 6;
    int d  = threadIdx.x & 63;
    int n = blockIdx.x*4 + tl;
    __shared__ float as[4][DH_];
    as[tl][d] = g_attn[(h*NT_ + n)*DH_ + d];
    __syncthreads();
    int e = g_idx[n*H_ + h];
    const float* W = Wo + ((size_t)(h*EA_+e))*DH_*DH_;
    float acc = 0.f;
    #pragma unroll 16
    for (int k = 0; k < DH_; k++) acc += as[tl][k]*W[k*DH_ + d];
    int o = n*D_ + h*DH_ + d;
    float val = x[o] + acc;
    g_x1[o] = val;
    out[o] = val;
}

// ---------------- Q/K projection: 128x64 tiles, pipelined --------------------
__global__ void qk_tc(const float* __restrict__ Wq, const float* __restrict__ Wk) {
    const float* Bw = blockIdx.z ? Wk : Wq;
    float* C = blockIdx.z ? g_kv : g_q;
    __shared__ unsigned As[128][20];
    __shared__ unsigned Bs[16][68];
    int tid = threadIdx.x;
    int row0 = blockIdx.y*128, col0 = blockIdx.x*64;
    int lane = tid & 31, wid = tid >> 5;
    int wm = (wid & 1)*64, wn = (wid >> 1)*16;
    int grp = lane >> 2, tig = lane & 3;
    int ar = tid >> 2, ac4 = (tid & 3)*4;
    int br = tid >> 4, bc4 = (tid & 15)*4;
    float acc[4][2][4];
    #pragma unroll
    for (int i = 0; i < 4; i++) for (int j = 0; j < 2; j++) for (int q = 0; q < 4; q++) acc[i][j][q] = 0.f;
    float4 aR[2], bR;
    #pragma unroll
    for (int rr = 0; rr < 2; rr++)
        aR[rr] = *(const float4*)&g_xn1[(row0+ar+rr*64)*D_ + ac4];
    bR = *(const float4*)&Bw[(size_t)br*D_ + col0 + bc4];
    for (int k0 = 0; k0 < D_; k0 += 16) {
        #pragma unroll
        for (int rr = 0; rr < 2; rr++)
            st4(&As[ar+rr*64][ac4], aR[rr]);
        st4(&Bs[br][bc4], bR);
        __syncthreads();
        if (k0 + 16 < D_) {
            #pragma unroll
            for (int rr = 0; rr < 2; rr++)
                aR[rr] = *(const float4*)&g_xn1[(row0+ar+rr*64)*D_ + k0+16 + ac4];
            bR = *(const float4*)&Bw[(size_t)(k0+16+br)*D_ + col0 + bc4];
        }
        #pragma unroll
        for (int kk = 0; kk < 16; kk += 8) {
            unsigned a[4][4], b[2][2];
            #pragma unroll
            for (int mi = 0; mi < 4; mi++) {
                int row = wm + mi*16 + grp, col = kk + tig;
                a[mi][0] = As[row][col];   a[mi][1] = As[row+8][col];
                a[mi][2] = As[row][col+4]; a[mi][3] = As[row+8][col+4];
            }
            #pragma unroll
            for (int nj = 0; nj < 2; nj++) {
                int bc = wn + nj*8 + grp;
                b[nj][0] = Bs[kk+tig][bc]; b[nj][1] = Bs[kk+4+tig][bc];
            }
            #pragma unroll
            for (int mi = 0; mi < 4; mi++)
                #pragma unroll
                for (int nj = 0; nj < 2; nj++) mma8(acc[mi][nj], a[mi], b[nj]);
        }
        __syncthreads();
    }
    #pragma unroll
    for (int mi = 0; mi < 4; mi++)
        #pragma unroll
        for (int nj = 0; nj < 2; nj++) {
            int r = row0 + wm + mi*16 + grp, c = col0 + wn + nj*8 + tig*2;
            C[r*D_ + c]     = acc[mi][nj][0];
            C[r*D_ + c+1]   = acc[mi][nj][1];
            C[(r+8)*D_ + c]   = acc[mi][nj][2];
            C[(r+8)*D_ + c+1] = acc[mi][nj][3];
        }
}

// ---------------- scores (fully-masked tiles skipped) ------------------------
__global__ void scores_tc(const float* __restrict__ mask) {
    int bh = blockIdx.z;
    int s0 = blockIdx.y*128, t0 = blockIdx.x*128;
    if (t0 >= s0 + 128) return;
    float* P = g_p + (size_t)bh*S_*S_;
    int tid = threadIdx.x;
    int b = bh / H_, h = bh % H_;
    const float* Qb = g_q  + (size_t)(b*S_)*D_ + h*DH_;
    const float* Kb = g_kv + (size_t)(b*S_)*D_ + h*DH_;
    __shared__ unsigned Qs[128][20];
    __shared__ unsigned Ks[128][20];
    int lane = tid & 31, wid = tid >> 5;
    int wm = (wid & 1)*64, wn = (wid >> 1)*32;
    int grp = lane >> 2, tig = lane & 3;
    int ar = tid >> 2, ac4 = (tid & 3)*4;
    float acc[4][4][4];
    #pragma unroll
    for (int i = 0; i < 4; i++) for (int j = 0; j < 4; j++) for (int q = 0; q < 4; q++) acc[i][j][q] = 0.f;
    for (int k0 = 0; k0 < DH_; k0 += 16) {
        #pragma unroll
        for (int rr = 0; rr < 2; rr++) {
            int r = ar + rr*64;
            st4(&Qs[r][ac4], *(const float4*)&Qb[(s0+r)*D_ + k0 + ac4]);
            st4(&Ks[r][ac4], *(const float4*)&Kb[(t0+r)*D_ + k0 + ac4]);
        }
        __syncthreads();
        #pragma unroll
        for (int kk = 0; kk < 16; kk += 8) {
            unsigned a[4][4], b2[4][2];
            #pragma unroll
            for (int mi = 0; mi < 4; mi++) {
                int row = wm + mi*16 + grp, col = kk + tig;
                a[mi][0] = Qs[row][col];   a[mi][1] = Qs[row+8][col];
                a[mi][2] = Qs[row][col+4]; a[mi][3] = Qs[row+8][col+4];
            }
            #pragma unroll
            for (int nj = 0; nj < 4; nj++) {
                int bc = wn + nj*8 + grp;
                b2[nj][0] = Ks[bc][kk+tig]; b2[nj][1] = Ks[bc][kk+4+tig];
            }
            #pragma unroll
            for (int mi = 0; mi < 4; mi++)
                #pragma unroll
                for (int nj = 0; nj < 4; nj++) mma8(acc[mi][nj], a[mi], b2[nj]);
        }
        __syncthreads();
    }
    #pragma unroll
    for (int mi = 0; mi < 4; mi++)
        #pragma unroll
        for (int nj = 0; nj < 4; nj++) {
            int s = s0 + wm + mi*16 + grp, t = t0 + wn + nj*8 + tig*2;
            P[(size_t)s*S_ + t]       = acc[mi][nj][0]*0.125f + mask[s*S_ + t];
            P[(size_t)s*S_ + t+1]     = acc[mi][nj][1]*0.125f + mask[s*S_ + t+1];
            P[(size_t)(s+8)*S_ + t]   = acc[mi][nj][2]*0.125f + mask[(s+8)*S_ + t];
            P[(size_t)(s+8)*S_ + t+1] = acc[mi][nj][3]*0.125f + mask[(s+8)*S_ + t+1];
        }
}

// ---------------- softmax: causal (loads predicated) -------------------------
__global__ void softmax_kernel() {
    int wid = threadIdx.x >> 5, lane = threadIdx.x & 31;
    size_t row = (size_t)blockIdx.x*8 + wid;
    int s_row = (int)(row & (S_-1));
    float* pr = g_p + row*S_;
    float v[16];
    float m = -1e30f;
    #pragma unroll
    for (int i = 0; i < 16; i++) {
        int t = lane + 32*i;
        v[i] = (t <= s_row) ? pr[t] : -1e30f;
        m = fmaxf(m, v[i]);
    }
    m = warp_max(m);
    float s = 0.f;
    #pragma unroll
    for (int i = 0; i < 16; i++) { v[i] = expf(v[i]-m); s += v[i]; }
    float inv = 1.f/warp_sum(s);
    #pragma unroll
    for (int i = 0; i < 16; i++) pr[lane + 32*i] = v[i]*inv;
}

// ---------------- attn = P^T @ V: 128-wide t-tiles, pipelined ----------------
__global__ void attn_tc() {
    int bh = blockIdx.z; int b = bh / H_, h = bh % H_;
    int t0 = blockIdx.x*128;
    const float* P = g_p + (size_t)bh*S_*S_;
    const float* V = g_vproj + (size_t)(h*NT_ + b*S_)*DH_;
    __shared__ unsigned Ps[16][132];
    __shared__ unsigned Vs[16][68];
    int tid = threadIdx.x;
    int lane = tid & 31, wid = tid >> 5;
    int wm = (wid & 3)*32, wn = (wid >> 2)*32;
    int grp = lane >> 2, tig = lane & 3;
    int pr_ = tid >> 5, pc4 = (tid & 31)*4;
    int vr = tid >> 4, vc4 = (tid & 15)*4;
    float acc[2][4][4];
    #pragma unroll
    for (int i = 0; i < 2; i++) for (int j = 0; j < 4; j++) for (int q = 0; q < 4; q++) acc[i][j][q] = 0.f;
    float4 pR[2], vR;
    #pragma unroll
    for (int rr = 0; rr < 2; rr++)
        pR[rr] = *(const float4*)&P[(size_t)(t0+pr_+rr*8)*S_ + t0 + pc4];
    vR = *(const float4*)&V[(t0+vr)*DH_ + vc4];
    for (int s0 = t0; s0 < S_; s0 += 16) {
        #pragma unroll
        for (int rr = 0; rr < 2; rr++)
            st4(&Ps[pr_+rr*8][pc4], pR[rr]);
        st4(&Vs[vr][vc4], vR);
        __syncthreads();
        if (s0 + 16 < S_) {
            #pragma unroll
            for (int rr = 0; rr < 2; rr++)
                pR[rr] = *(const float4*)&P[(size_t)(s0+16+pr_+rr*8)*S_ + t0 + pc4];
            vR = *(const float4*)&V[(s0+16+vr)*DH_ + vc4];
        }
        #pragma unroll
        for (int kk = 0; kk < 16; kk += 8) {
            unsigned a[2][4], b2[4][2];
            #pragma unroll
            for (int mi = 0; mi < 2; mi++) {
                int m = wm + mi*16 + grp;
                a[mi][0] = Ps[kk+tig][m];   a[mi][1] = Ps[kk+tig][m+8];
                a[mi][2] = Ps[kk+4+tig][m]; a[mi][3] = Ps[kk+4+tig][m+8];
            }
            #pragma unroll
            for (int nj = 0; nj < 4; nj++) {
                int bc = wn + nj*8 + grp;
                b2[nj][0] = Vs[kk+tig][bc]; b2[nj][1] = Vs[kk+4+tig][bc];
            }
            #pragma unroll
            for (int mi = 0; mi < 2; mi++)
                #pragma unroll
                for (int nj = 0; nj < 4; nj++) mma8(acc[mi][nj], a[mi], b2[nj]);
        }
        __syncthreads();
    }
    #pragma unroll
    for (int mi = 0; mi < 2; mi++)
        #pragma unroll
        for (int nj = 0; nj < 4; nj++) {
            int t = t0 + wm + mi*16 + grp, d = wn + nj*8 + tig*2;
            float* O = g_attn + (size_t)(h*NT_ + b*S_)*DH_;
            O[t*DH_ + d]       = acc[mi][nj][0];
            O[t*DH_ + d+1]     = acc[mi][nj][1];
            O[(t+8)*DH_ + d]   = acc[mi][nj][2];
            O[(t+8)*DH_ + d+1] = acc[mi][nj][3];
        }
}

// ---------------- fused gate: top2 + FCFS dispatch + weights -----------------
__global__ void gate_dispatch_kernel() {
    int tid = threadIdx.x;
    int wid = tid >> 5, lane = tid & 31;
    for (int n = tid; n < NT_; n += 256) {
        const float* gv = &g_glf[n*64];
        int i0 = 0; float v0 = gv[0];
        #pragma unroll
        for (int j = 1; j < EF_; j++) if (gv[j] > v0) { v0 = gv[j]; i0 = j; }
        int i1 = -1; float v1 = -1e30f;
        #pragma unroll
        for (int j = 0; j < EF_; j++) { if (j == i0) continue; if (gv[j] > v1) { v1 = gv[j]; i1 = j; } }
        float e = expf(v1 - v0);
        float inv = 1.f/(1.f + e);
        g_topidx[n*2]   = i0;  g_topidx[n*2+1] = i1;
        g_rawp[n*2]     = inv; g_rawp[n*2+1]   = e*inv;
    }
    for (int i = tid; i < NT_*K_; i += 256) g_keep[i] = 0;
    __syncthreads();
    int e = wid;
    int c = 0;
    for (int base = 0; base < NT_*K_; base += 32) {
        int idx = g_topidx[base + lane];
        unsigned m = __ballot_sync(0xffffffffu, idx == e);
        if (idx == e) {
            int pos = c + __popc(m & ((1u << lane) - 1));
            if (pos < CAP_) { g_slot[e*CAP_ + pos] = base + lane; g_keep[base + lane] = 1; }
        }
        c += __popc(m);
    }
    if (lane == 0) g_ecnt[e] = (c < CAP_) ? c : CAP_;
    __syncthreads();
    for (int n = tid; n < NT_; n += 256) {
        float p0 = g_keep[2*n]   ? g_rawp[2*n]   : 0.f;
        float p1 = g_keep[2*n+1] ? g_rawp[2*n+1] : 0.f;
        float s = p0 + p1 + 1e-9f;
        float w0 = p0/s, w1 = p1/s;
        g_w[2*n] = w0; g_w[2*n+1] = w1;
        if (w0 > 0.f) atomicAdd(&g_eimp[g_topidx[2*n]],   w0);
        if (w1 > 0.f) atomicAdd(&g_eimp[g_topidx[2*n+1]], w1);
    }
}

// ---------------- FF GEMM 1: M=160 x N=64 tiles (2 blocks/SM) ----------------
__global__ void __launch_bounds__(256, 2) ff1_tc(const float* __restrict__ W1) {
    int e = blockIdx.z;
    int cnt = g_ecnt[e];
    int col0 = blockIdx.x*64;
    __shared__ int toks[192];
    __shared__ unsigned As[192][20];
    __shared__ unsigned Bs[16][68];
    int tid = threadIdx.x;
    if (tid < 192) toks[tid] = (tid < cnt) ? (g_slot[e*CAP_ + tid] >> 1) : -1;
    __syncthreads();
    const float* W = W1 + (size_t)e*D_*DFF_;
    int lane = tid & 31, wid = tid >> 5;
    int wm = (wid & 1)*80, wn = (wid >> 1)*16;
    int grp = lane >> 2, tig = lane & 3;
    int ar = tid >> 2, ac4 = (tid & 3)*4;
    int br = tid >> 4, bc4 = (tid & 15)*4;
    int tok[3];
    tok[0] = toks[ar]; tok[1] = toks[ar+64]; tok[2] = toks[ar+128];
    float acc[5][2][4];
    #pragma unroll
    for (int i = 0; i < 5; i++) for (int j = 0; j < 2; j++) for (int q = 0; q < 4; q++) acc[i][j][q] = 0.f;
    float4 aR[3], bR;
    float4 z4 = {0.f,0.f,0.f,0.f};
    #pragma unroll
    for (int rr = 0; rr < 3; rr++)
        aR[rr] = (tok[rr] >= 0) ? *(const float4*)&g_xn2[tok[rr]*D_ + ac4] : z4;
    bR = *(const float4*)&W[(size_t)br*DFF_ + col0 + bc4];
    for (int k0 = 0; k0 < D_; k0 += 16) {
        #pragma unroll
        for (int rr = 0; rr < 3; rr++)
            st4(&As[ar+rr*64][ac4], aR[rr]);
        st4(&Bs[br][bc4], bR);
        __syncthreads();
        if (k0 + 16 < D_) {
            #pragma unroll
            for (int rr = 0; rr < 3; rr++)
                aR[rr] = (tok[rr] >= 0) ? *(const float4*)&g_xn2[tok[rr]*D_ + k0+16 + ac4] : z4;
            bR = *(const float4*)&W[(size_t)(k0+16+br)*DFF_ + col0 + bc4];
        }
        #pragma unroll
        for (int kk = 0; kk < 16; kk += 8) {
            unsigned a[5][4], b2[2][2];
            #pragma unroll
            for (int mi = 0; mi < 5; mi++) {
                int row = wm + mi*16 + grp, col = kk + tig;
                a[mi][0] = As[row][col];   a[mi][1] = As[row+8][col];
                a[mi][2] = As[row][col+4]; a[mi][3] = As[row+8][col+4];
            }
            #pragma unroll
            for (int nj = 0; nj < 2; nj++) {
                int bc = wn + nj*8 + grp;
                b2[nj][0] = Bs[kk+tig][bc]; b2[nj][1] = Bs[kk+4+tig][bc];
            }
            #pragma unroll
            for (int mi = 0; mi < 5; mi++)
                #pragma unroll
                for (int nj = 0; nj < 2; nj++) mma8(acc[mi][nj], a[mi], b2[nj]);
        }
        __syncthreads();
    }
    #pragma unroll
    for (int mi = 0; mi < 5; mi++)
        #pragma unroll
        for (int nj = 0; nj < 2; nj++) {
            int rl = wm + mi*16 + grp;
            int c = col0 + wn + nj*8 + tig*2;
            if (rl < cnt) {
                float* hp = &g_hmid[(size_t)(e*CAP_ + rl)*DFF_ + c];
                hp[0] = fmaxf(acc[mi][nj][0], 0.f);
                hp[1] = fmaxf(acc[mi][nj][1], 0.f);
            }
            if (rl + 8 < cnt) {
                float* hp = &g_hmid[(size_t)(e*CAP_ + rl + 8)*DFF_ + c];
                hp[0] = fmaxf(acc[mi][nj][2], 0.f);
                hp[1] = fmaxf(acc[mi][nj][3], 0.f);
            }
        }
}

// ---------------- FF GEMM 2: M=160 x N=64 tiles, K-split x3 ------------------
__global__ void __launch_bounds__(256, 2) ff2_tc(const float* __restrict__ W2, float* __restrict__ out) {
    int e = blockIdx.z;
    int cnt = g_ecnt[e];
    int col0 = blockIdx.x*64;
    int kbase = blockIdx.y*(DFF_/3);
    __shared__ unsigned As[192][20];
    __shared__ unsigned Bs[16][68];
    int tid = threadIdx.x;
    const float* A = g_hmid + (size_t)e*CAP_*DFF_;
    const float* W = W2 + (size_t)e*DFF_*D_;
    int lane = tid & 31, wid = tid >> 5;
    int wm = (wid & 1)*80, wn = (wid >> 1)*16;
    int grp = lane >> 2, tig = lane & 3;
    int ar = tid >> 2, ac4 = (tid & 3)*4;
    int br = tid >> 4, bc4 = (tid & 15)*4;
    int ok[3];
    ok[0] = (ar < cnt); ok[1] = (ar + 64 < cnt); ok[2] = (ar + 128 < cnt);
    float acc[5][2][4];
    #pragma unroll
    for (int i = 0; i < 5; i++) for (int j = 0; j < 2; j++) for (int q = 0; q < 4; q++) acc[i][j][q] = 0.f;
    float4 aR[3], bR;
    float4 z4 = {0.f,0.f,0.f,0.f};
    #pragma unroll
    for (int rr = 0; rr < 3; rr++)
        aR[rr] = ok[rr] ? *(const float4*)&A[(size_t)(ar+rr*64)*DFF_ + kbase + ac4] : z4;
    bR = *(const float4*)&W[(size_t)(kbase+br)*D_ + col0 + bc4];
    for (int k0 = kbase; k0 < kbase + DFF_/3; k0 += 16) {
        #pragma unroll
        for (int rr = 0; rr < 3; rr++)
            st4(&As[ar+rr*64][ac4], aR[rr]);
        st4(&Bs[br][bc4], bR);
        __syncthreads();
        if (k0 + 16 < kbase + DFF_/3) {
            #pragma unroll
            for (int rr = 0; rr < 3; rr++)
                aR[rr] = ok[rr] ? *(const float4*)&A[(size_t)(ar+rr*64)*DFF_ + k0+16 + ac4] : z4;
            bR = *(const float4*)&W[(size_t)(k0+16+br)*D_ + col0 + bc4];
        }
        #pragma unroll
        for (int kk = 0; kk < 16; kk += 8) {
            unsigned a[5][4], b2[2][2];
            #pragma unroll
            for (int mi = 0; mi < 5; mi++) {
                int row = wm + mi*16 + grp, col = kk + tig;
                a[mi][0] = As[row][col];   a[mi][1] = As[row+8][col];
                a[mi][2] = As[row][col+4]; a[mi][3] = As[row+8][col+4];
            }
            #pragma unroll
            for (int nj = 0; nj < 2; nj++) {
                int bc = wn + nj*8 + grp;
                b2[nj][0] = Bs[kk+tig][bc]; b2[nj][1] = Bs[kk+4+tig][bc];
            }
            #pragma unroll
            for (int mi = 0; mi < 5; mi++)
                #pragma unroll
                for (int nj = 0; nj < 2; nj++) mma8(acc[mi][nj], a[mi], b2[nj]);
        }
        __syncthreads();
    }
    #pragma unroll
    for (int mi = 0; mi < 5; mi++)
        #pragma unroll
        for (int nj = 0; nj < 2; nj++) {
            int rl = wm + mi*16 + grp;
            int c = col0 + wn + nj*8 + tig*2;
            if (rl < cnt) {
                int slot = g_slot[e*CAP_ + rl];
                int tok = slot >> 1;
                float w = g_w[slot];
                atomicAdd(&out[tok*D_ + c],   w*acc[mi][nj][0]);
                atomicAdd(&out[tok*D_ + c+1], w*acc[mi][nj][1]);
            }
            if (rl + 8 < cnt) {
                int slot = g_slot[e*CAP_ + rl + 8];
                int tok = slot >> 1;
                float w = g_w[slot];
                atomicAdd(&out[tok*D_ + c],   w*acc[mi][nj][2]);
                atomicAdd(&out[tok*D_ + c+1], w*acc[mi][nj][3]);
            }
        }
}

// ---------------- aux --------------------------------------------------------
__global__ void aux_kernel(float* __restrict__ out, int out_size) {
    if (blockIdx.x != 0 || threadIdx.x != 0) return;
    float ema[H_*EA_];
    float es = 0.f;
    for (int i = 0; i < H_*EA_; i++) { ema[i] = 0.01f*(float)g_headcnt[i]/(float)NT_; es += ema[i]; }
    float aux1 = 0.f;
    for (int i = 0; i < H_*EA_; i++) { float pr = ema[i]/(es + 1e-9f); aux1 += pr*pr; }
    aux1 *= (float)(EA_*H_);
    float sc = 0.f, si = 0.f;
    for (int e = 0; e < EF_; e++) { sc += (float)g_ecnt[e]; si += g_eimp[e]; }
    float aux2 = 0.f;
    for (int e = 0; e < EF_; e++)
        aux2 += ((float)g_ecnt[e]/(sc + 1e-9f)) * (g_eimp[e]/(si + 1e-9f));
    aux2 *= (float)EF_;
    float a = aux1 + aux2;
    for (int i = BSD_; i < out_size; i++) out[i] = a;
}

// ---------------- launch: fork/join DAG over two streams ---------------------
extern "C" void kernel_launch(void* const* d_in, const int* in_sizes, int n_in,
                              void* d_out, int out_size) {
    const float* x    = (const float*)d_in[0];
    const float* mask = (const float*)d_in[1];
    const float* ln1g = (const float*)d_in[2];
    const float* ln1b = (const float*)d_in[3];
    const float* ln2g = (const float*)d_in[4];
    const float* ln2b = (const float*)d_in[5];
    const float* Wq   = (const float*)d_in[6];
    const float* Wk   = (const float*)d_in[7];
    const float* Wv   = (const float*)d_in[8];
    const float* Wo   = (const float*)d_in[9];
    const float* rw   = (const float*)d_in[10];
    const float* gw   = (const float*)d_in[11];
    const float* W1   = (const float*)d_in[12];
    const float* W2   = (const float*)d_in[13];
    float* out = (float*)d_out;

    cudaStream_t s1;
    cudaEvent_t evA, evB;
    cudaStreamCreateWithFlags(&s1, cudaStreamNonBlocking);
    cudaEventCreateWithFlags(&evA, cudaEventDisableTiming);
    cudaEventCreateWithFlags(&evB, cudaEventDisableTiming);

    init_kernel<<<256, 256>>>();
    ln_kernel<<<NT_/8, 256>>>(x, ln1g, ln1b, 0);

    // fork: side chain (router -> argmax -> vproj) under qk/scores/softmax
    cudaEventRecord(evA, 0);
    cudaStreamWaitEvent(s1, evA, 0);
    smalln_gemm<<<dim3(NT_/64, D_/64), 256, 0, s1>>>(rw, H_*EA_, 0);
    argmax_router<<<(NT_*H_ + 255)/256, 256, 0, s1>>>();
    vproj_kernel<<<dim3(NT_/4, H_), 256, 0, s1>>>(Wv);
    cudaEventRecord(evB, s1);

    qk_tc<<<dim3(D_/64, NT_/128, 2), 256>>>(Wq, Wk);
    scores_tc<<<dim3(S_/128, S_/128, B_*H_), 256>>>(mask);
    softmax_kernel<<<B_*H_*S_/8, 256>>>();

    cudaStreamWaitEvent(0, evB, 0);
    attn_tc<<<dim3(S_/128, 1, B_*H_), 256>>>();
    oproj_kernel<<<dim3(NT_/4, H_), 256>>>(x, Wo, out);
    ln_kernel<<<NT_/8, 256>>>(x, ln2g, ln2b, 1);
    smalln_gemm<<<dim3(NT_/64, D_/64), 256>>>(gw, EF_, 1);
    gate_dispatch_kernel<<<1, 256>>>();
    ff1_tc<<<dim3(DFF_/64, 1, EF_), 256>>>(W1);
    ff2_tc<<<dim3(D_/64, 3, EF_), 256>>>(W2, out);
    aux_kernel<<<1, 32>>>(out, out_size);
}

// round 16
// speedup vs baseline: 1.0941x; 1.0941x over previous
#include <cuda_runtime.h>
#include <math.h>

#define B_ 2
#define S_ 512
#define D_ 768
#define H_ 12
#define DH_ 64
#define EA_ 4
#define EF_ 8
#define DFF_ 3072
#define K_ 2
#define NT_ 1024
#define CAP_ 160
#define BSD_ 786432

// ---------------- scratch ----------------------------------------------------
__device__ float g_xn1[NT_*D_];
__device__ float g_q[NT_*D_];
__device__ float g_kv[NT_*D_];
__device__ int   g_idx[NT_*H_];
__device__ int   g_headcnt[H_*EA_];
__device__ float g_vproj[H_*NT_*DH_];
__device__ float g_p[(size_t)B_*H_*S_*S_];
__device__ float g_x1[NT_*D_];
__device__ float g_xn2[NT_*D_];
__device__ float g_glr[NT_*64];
__device__ float g_glf[NT_*64];
__device__ int   g_topidx[NT_*K_];
__device__ float g_rawp[NT_*K_];
__device__ float g_w[NT_*K_];
__device__ int   g_keep[NT_*K_];
__device__ int   g_slot[EF_*CAP_];
__device__ int   g_ecnt[EF_];
__device__ float g_eimp[EF_];
__device__ float g_hmid[EF_*CAP_*DFF_];

#define g_attn g_xn1   // liveness-disjoint alias

// ---------------- mma helpers -----------------------------------------------
__device__ __forceinline__ unsigned f2tf(float f) {
    unsigned u; asm("cvt.rna.tf32.f32 %0, %1;" : "=r"(u) : "f"(f)); return u;
}
__device__ __forceinline__ void mma8(float* c, const unsigned* a, const unsigned* b) {
    asm("mma.sync.aligned.m16n8k8.row.col.f32.tf32.tf32.f32 "
        "{%0,%1,%2,%3},{%4,%5,%6,%7},{%8,%9},{%0,%1,%2,%3};"
        : "+f"(c[0]), "+f"(c[1]), "+f"(c[2]), "+f"(c[3])
        : "r"(a[0]), "r"(a[1]), "r"(a[2]), "r"(a[3]), "r"(b[0]), "r"(b[1]));
}
__device__ __forceinline__ void st4(unsigned* dst, float4 v) {
    uint4 u; u.x = f2tf(v.x); u.y = f2tf(v.y); u.z = f2tf(v.z); u.w = f2tf(v.w);
    *(uint4*)dst = u;
}
__device__ __forceinline__ float warp_sum(float v) {
    #pragma unroll
    for (int o = 16; o; o >>= 1) v += __shfl_xor_sync(0xffffffffu, v, o);
    return v;
}
__device__ __forceinline__ float warp_max(float v) {
    #pragma unroll
    for (int o = 16; o; o >>= 1) v = fmaxf(v, __shfl_xor_sync(0xffffffffu, v, o));
    return v;
}

// ---------------- init -------------------------------------------------------
__global__ void init_kernel() {
    int t = blockIdx.x*blockDim.x + threadIdx.x;
    if (t < H_*EA_) g_headcnt[t] = 0;
    if (t < EF_)    g_eimp[t] = 0.f;
    if (t < NT_*64) { g_glr[t] = 0.f; g_glf[t] = 0.f; }
}

// ---------------- layernorm --------------------------------------------------
__global__ void ln_kernel(const float* __restrict__ xext,
                          const float* __restrict__ g,
                          const float* __restrict__ b, int which) {
    int wid = threadIdx.x >> 5, lane = threadIdx.x & 31;
    int row = blockIdx.x*8 + wid;
    const float* xr = (which == 0 ? xext : g_x1) + row*D_;
    float* outr = (which == 0 ? g_xn1 : g_xn2) + row*D_;
    float v[24];
    float s = 0.f;
    #pragma unroll
    for (int i = 0; i < 24; i++) { v[i] = xr[lane + 32*i]; s += v[i]; }
    float mu = warp_sum(s) * (1.f/D_);
    float var = 0.f;
    #pragma unroll
    for (int i = 0; i < 24; i++) { float d = v[i]-mu; var += d*d; }
    float inv = rsqrtf(warp_sum(var) * (1.f/D_) + 1e-5f);
    #pragma unroll
    for (int i = 0; i < 24; i++) {
        int c = lane + 32*i;
        outr[c] = (v[i]-mu)*inv*g[c] + b[c];
    }
}

// ---------------- small-N fp32 GEMM: 64x64 tiles -----------------------------
__global__ void smalln_gemm(const float* __restrict__ Bsrc, int ncols, int which) {
    const float* A = which ? g_xn2 : g_xn1;
    float* Cpad    = which ? g_glf : g_glr;
    __shared__ float As[64][17];
    __shared__ float Bs[16][68];
    int tid = threadIdx.x;
    int row0 = blockIdx.x*64;
    int kbase = blockIdx.y*64;
    int tx = tid & 63;
    int ty = tid >> 6;
    float acc[16];
    #pragma unroll
    for (int i = 0; i < 16; i++) acc[i] = 0.f;
    for (int k0 = kbase; k0 < kbase + 64; k0 += 16) {
        int ar = tid >> 2, ac4 = (tid & 3)*4;
        float4 va = *(const float4*)&A[(row0+ar)*D_ + k0 + ac4];
        As[ar][ac4]   = va.x;
        As[ar][ac4+1] = va.y;
        As[ar][ac4+2] = va.z;
        As[ar][ac4+3] = va.w;
        int bk = tid >> 4, bc4 = (tid & 15)*4;
        #pragma unroll
        for (int j = 0; j < 4; j++) {
            int c = bc4 + j;
            Bs[bk][c] = (c < ncols) ? Bsrc[(size_t)(k0+bk)*ncols + c] : 0.f;
        }
        __syncthreads();
        #pragma unroll
        for (int k = 0; k < 16; k++) {
            float bv = Bs[k][tx];
            #pragma unroll
            for (int i = 0; i < 16; i++) acc[i] += As[ty*16 + i][k]*bv;
        }
        __syncthreads();
    }
    #pragma unroll
    for (int i = 0; i < 16; i++)
        atomicAdd(&Cpad[(row0 + ty*16 + i)*64 + tx], acc[i]);
}

// ---------------- router argmax ----------------------------------------------
__global__ void argmax_router() {
    int id = blockIdx.x*256 + threadIdx.x;
    if (id >= NT_*H_) return;
    int n = id / H_, h = id % H_;
    const float* gv = &g_glr[n*64 + h*EA_];
    float best = gv[0]; int bi = 0;
    #pragma unroll
    for (int e = 1; e < EA_; e++) { float v = gv[e]; if (v > best) { best = v; bi = e; } }
    g_idx[n*H_ + h] = bi;
    atomicAdd(&g_headcnt[h*EA_ + bi], 1);
}

// ---------------- V projection -----------------------------------------------
__global__ void vproj_kernel(const float* __restrict__ Wv) {
    int h = blockIdx.y;
    int tl = threadIdx.x >> 6;
    int d  = threadIdx.x & 63;
    int n = blockIdx.x*4 + tl;
    __shared__ float xs[4][DH_];
    xs[tl][d] = g_xn1[n*D_ + h*DH_ + d];
    __syncthreads();
    int e = g_idx[n*H_ + h];
    const float* W = Wv + ((size_t)(h*EA_+e))*DH_*DH_;
    float acc = 0.f;
    #pragma unroll 16
    for (int k = 0; k < DH_; k++) acc += xs[tl][k]*W[k*DH_ + d];
    g_vproj[(h*NT_ + n)*DH_ + d] = acc;
}

// ---------------- O projection + residual ------------------------------------
__global__ void oproj_kernel(const float* __restrict__ x, const float* __restrict__ Wo,
                             float* __restrict__ out) {
    int h = blockIdx.y;
    int tl = threadIdx.x >> 6;
    int d  = threadIdx.x & 63;
    int n = blockIdx.x*4 + tl;
    __shared__ float as[4][DH_];
    as[tl][d] = g_attn[(h*NT_ + n)*DH_ + d];
    __syncthreads();
    int e = g_idx[n*H_ + h];
    const float* W = Wo + ((size_t)(h*EA_+e))*DH_*DH_;
    float acc = 0.f;
    #pragma unroll 16
    for (int k = 0; k < DH_; k++) acc += as[tl][k]*W[k*DH_ + d];
    int o = n*D_ + h*DH_ + d;
    float val = x[o] + acc;
    g_x1[o] = val;
    out[o] = val;
}

// ---------------- Q/K projection: 128x64 tiles, pipelined --------------------
__global__ void qk_tc(const float* __restrict__ Wq, const float* __restrict__ Wk) {
    const float* Bw = blockIdx.z ? Wk : Wq;
    float* C = blockIdx.z ? g_kv : g_q;
    __shared__ unsigned As[128][20];
    __shared__ unsigned Bs[16][68];
    int tid = threadIdx.x;
    int row0 = blockIdx.y*128, col0 = blockIdx.x*64;
    int lane = tid & 31, wid = tid >> 5;
    int wm = (wid & 1)*64, wn = (wid >> 1)*16;
    int grp = lane >> 2, tig = lane & 3;
    int ar = tid >> 2, ac4 = (tid & 3)*4;
    int br = tid >> 4, bc4 = (tid & 15)*4;
    float acc[4][2][4];
    #pragma unroll
    for (int i = 0; i < 4; i++) for (int j = 0; j < 2; j++) for (int q = 0; q < 4; q++) acc[i][j][q] = 0.f;
    float4 aR[2], bR;
    #pragma unroll
    for (int rr = 0; rr < 2; rr++)
        aR[rr] = *(const float4*)&g_xn1[(row0+ar+rr*64)*D_ + ac4];
    bR = *(const float4*)&Bw[(size_t)br*D_ + col0 + bc4];
    for (int k0 = 0; k0 < D_; k0 += 16) {
        #pragma unroll
        for (int rr = 0; rr < 2; rr++)
            st4(&As[ar+rr*64][ac4], aR[rr]);
        st4(&Bs[br][bc4], bR);
        __syncthreads();
        if (k0 + 16 < D_) {
            #pragma unroll
            for (int rr = 0; rr < 2; rr++)
                aR[rr] = *(const float4*)&g_xn1[(row0+ar+rr*64)*D_ + k0+16 + ac4];
            bR = *(const float4*)&Bw[(size_t)(k0+16+br)*D_ + col0 + bc4];
        }
        #pragma unroll
        for (int kk = 0; kk < 16; kk += 8) {
            unsigned a[4][4], b[2][2];
            #pragma unroll
            for (int mi = 0; mi < 4; mi++) {
                int row = wm + mi*16 + grp, col = kk + tig;
                a[mi][0] = As[row][col];   a[mi][1] = As[row+8][col];
                a[mi][2] = As[row][col+4]; a[mi][3] = As[row+8][col+4];
            }
            #pragma unroll
            for (int nj = 0; nj < 2; nj++) {
                int bc = wn + nj*8 + grp;
                b[nj][0] = Bs[kk+tig][bc]; b[nj][1] = Bs[kk+4+tig][bc];
            }
            #pragma unroll
            for (int mi = 0; mi < 4; mi++)
                #pragma unroll
                for (int nj = 0; nj < 2; nj++) mma8(acc[mi][nj], a[mi], b[nj]);
        }
        __syncthreads();
    }
    #pragma unroll
    for (int mi = 0; mi < 4; mi++)
        #pragma unroll
        for (int nj = 0; nj < 2; nj++) {
            int r = row0 + wm + mi*16 + grp, c = col0 + wn + nj*8 + tig*2;
            C[r*D_ + c]     = acc[mi][nj][0];
            C[r*D_ + c+1]   = acc[mi][nj][1];
            C[(r+8)*D_ + c]   = acc[mi][nj][2];
            C[(r+8)*D_ + c+1] = acc[mi][nj][3];
        }
}

// ---------------- scores (fully-masked tiles skipped) ------------------------
__global__ void scores_tc(const float* __restrict__ mask) {
    int bh = blockIdx.z;
    int s0 = blockIdx.y*128, t0 = blockIdx.x*128;
    if (t0 >= s0 + 128) return;
    float* P = g_p + (size_t)bh*S_*S_;
    int tid = threadIdx.x;
    int b = bh / H_, h = bh % H_;
    const float* Qb = g_q  + (size_t)(b*S_)*D_ + h*DH_;
    const float* Kb = g_kv + (size_t)(b*S_)*D_ + h*DH_;
    __shared__ unsigned Qs[128][20];
    __shared__ unsigned Ks[128][20];
    int lane = tid & 31, wid = tid >> 5;
    int wm = (wid & 1)*64, wn = (wid >> 1)*32;
    int grp = lane >> 2, tig = lane & 3;
    int ar = tid >> 2, ac4 = (tid & 3)*4;
    float acc[4][4][4];
    #pragma unroll
    for (int i = 0; i < 4; i++) for (int j = 0; j < 4; j++) for (int q = 0; q < 4; q++) acc[i][j][q] = 0.f;
    for (int k0 = 0; k0 < DH_; k0 += 16) {
        #pragma unroll
        for (int rr = 0; rr < 2; rr++) {
            int r = ar + rr*64;
            st4(&Qs[r][ac4], *(const float4*)&Qb[(s0+r)*D_ + k0 + ac4]);
            st4(&Ks[r][ac4], *(const float4*)&Kb[(t0+r)*D_ + k0 + ac4]);
        }
        __syncthreads();
        #pragma unroll
        for (int kk = 0; kk < 16; kk += 8) {
            unsigned a[4][4], b2[4][2];
            #pragma unroll
            for (int mi = 0; mi < 4; mi++) {
                int row = wm + mi*16 + grp, col = kk + tig;
                a[mi][0] = Qs[row][col];   a[mi][1] = Qs[row+8][col];
                a[mi][2] = Qs[row][col+4]; a[mi][3] = Qs[row+8][col+4];
            }
            #pragma unroll
            for (int nj = 0; nj < 4; nj++) {
                int bc = wn + nj*8 + grp;
                b2[nj][0] = Ks[bc][kk+tig]; b2[nj][1] = Ks[bc][kk+4+tig];
            }
            #pragma unroll
            for (int mi = 0; mi < 4; mi++)
                #pragma unroll
                for (int nj = 0; nj < 4; nj++) mma8(acc[mi][nj], a[mi], b2[nj]);
        }
        __syncthreads();
    }
    #pragma unroll
    for (int mi = 0; mi < 4; mi++)
        #pragma unroll
        for (int nj = 0; nj < 4; nj++) {
            int s = s0 + wm + mi*16 + grp, t = t0 + wn + nj*8 + tig*2;
            P[(size_t)s*S_ + t]       = acc[mi][nj][0]*0.125f + mask[s*S_ + t];
            P[(size_t)s*S_ + t+1]     = acc[mi][nj][1]*0.125f + mask[s*S_ + t+1];
            P[(size_t)(s+8)*S_ + t]   = acc[mi][nj][2]*0.125f + mask[(s+8)*S_ + t];
            P[(size_t)(s+8)*S_ + t+1] = acc[mi][nj][3]*0.125f + mask[(s+8)*S_ + t+1];
        }
}

// ---------------- softmax: causal (loads predicated) -------------------------
__global__ void softmax_kernel() {
    int wid = threadIdx.x >> 5, lane = threadIdx.x & 31;
    size_t row = (size_t)blockIdx.x*8 + wid;
    int s_row = (int)(row & (S_-1));
    float* pr = g_p + row*S_;
    float v[16];
    float m = -1e30f;
    #pragma unroll
    for (int i = 0; i < 16; i++) {
        int t = lane + 32*i;
        v[i] = (t <= s_row) ? pr[t] : -1e30f;
        m = fmaxf(m, v[i]);
    }
    m = warp_max(m);
    float s = 0.f;
    #pragma unroll
    for (int i = 0; i < 16; i++) { v[i] = expf(v[i]-m); s += v[i]; }
    float inv = 1.f/warp_sum(s);
    #pragma unroll
    for (int i = 0; i < 16; i++) pr[lane + 32*i] = v[i]*inv;
}

// ---------------- attn = P^T @ V: 128-wide t-tiles, pipelined ----------------
__global__ void attn_tc() {
    int bh = blockIdx.z; int b = bh / H_, h = bh % H_;
    int t0 = blockIdx.x*128;
    const float* P = g_p + (size_t)bh*S_*S_;
    const float* V = g_vproj + (size_t)(h*NT_ + b*S_)*DH_;
    __shared__ unsigned Ps[16][132];
    __shared__ unsigned Vs[16][68];
    int tid = threadIdx.x;
    int lane = tid & 31, wid = tid >> 5;
    int wm = (wid & 3)*32, wn = (wid >> 2)*32;
    int grp = lane >> 2, tig = lane & 3;
    int pr_ = tid >> 5, pc4 = (tid & 31)*4;
    int vr = tid >> 4, vc4 = (tid & 15)*4;
    float acc[2][4][4];
    #pragma unroll
    for (int i = 0; i < 2; i++) for (int j = 0; j < 4; j++) for (int q = 0; q < 4; q++) acc[i][j][q] = 0.f;
    float4 pR[2], vR;
    #pragma unroll
    for (int rr = 0; rr < 2; rr++)
        pR[rr] = *(const float4*)&P[(size_t)(t0+pr_+rr*8)*S_ + t0 + pc4];
    vR = *(const float4*)&V[(t0+vr)*DH_ + vc4];
    for (int s0 = t0; s0 < S_; s0 += 16) {
        #pragma unroll
        for (int rr = 0; rr < 2; rr++)
            st4(&Ps[pr_+rr*8][pc4], pR[rr]);
        st4(&Vs[vr][vc4], vR);
        __syncthreads();
        if (s0 + 16 < S_) {
            #pragma unroll
            for (int rr = 0; rr < 2; rr++)
                pR[rr] = *(const float4*)&P[(size_t)(s0+16+pr_+rr*8)*S_ + t0 + pc4];
            vR = *(const float4*)&V[(s0+16+vr)*DH_ + vc4];
        }
        #pragma unroll
        for (int kk = 0; kk < 16; kk += 8) {
            unsigned a[2][4], b2[4][2];
            #pragma unroll
            for (int mi = 0; mi < 2; mi++) {
                int m = wm + mi*16 + grp;
                a[mi][0] = Ps[kk+tig][m];   a[mi][1] = Ps[kk+tig][m+8];
                a[mi][2] = Ps[kk+4+tig][m]; a[mi][3] = Ps[kk+4+tig][m+8];
            }
            #pragma unroll
            for (int nj = 0; nj < 4; nj++) {
                int bc = wn + nj*8 + grp;
                b2[nj][0] = Vs[kk+tig][bc]; b2[nj][1] = Vs[kk+4+tig][bc];
            }
            #pragma unroll
            for (int mi = 0; mi < 2; mi++)
                #pragma unroll
                for (int nj = 0; nj < 4; nj++) mma8(acc[mi][nj], a[mi], b2[nj]);
        }
        __syncthreads();
    }
    #pragma unroll
    for (int mi = 0; mi < 2; mi++)
        #pragma unroll
        for (int nj = 0; nj < 4; nj++) {
            int t = t0 + wm + mi*16 + grp, d = wn + nj*8 + tig*2;
            float* O = g_attn + (size_t)(h*NT_ + b*S_)*DH_;
            O[t*DH_ + d]       = acc[mi][nj][0];
            O[t*DH_ + d+1]     = acc[mi][nj][1];
            O[(t+8)*DH_ + d]   = acc[mi][nj][2];
            O[(t+8)*DH_ + d+1] = acc[mi][nj][3];
        }
}

// ---------------- fused gate: top2 + FCFS dispatch + weights -----------------
__global__ void gate_dispatch_kernel() {
    int tid = threadIdx.x;
    int wid = tid >> 5, lane = tid & 31;
    for (int n = tid; n < NT_; n += 256) {
        const float* gv = &g_glf[n*64];
        int i0 = 0; float v0 = gv[0];
        #pragma unroll
        for (int j = 1; j < EF_; j++) if (gv[j] > v0) { v0 = gv[j]; i0 = j; }
        int i1 = -1; float v1 = -1e30f;
        #pragma unroll
        for (int j = 0; j < EF_; j++) { if (j == i0) continue; if (gv[j] > v1) { v1 = gv[j]; i1 = j; } }
        float e = expf(v1 - v0);
        float inv = 1.f/(1.f + e);
        g_topidx[n*2]   = i0;  g_topidx[n*2+1] = i1;
        g_rawp[n*2]     = inv; g_rawp[n*2+1]   = e*inv;
    }
    for (int i = tid; i < NT_*K_; i += 256) g_keep[i] = 0;
    __syncthreads();
    int e = wid;
    int c = 0;
    for (int base = 0; base < NT_*K_; base += 32) {
        int idx = g_topidx[base + lane];
        unsigned m = __ballot_sync(0xffffffffu, idx == e);
        if (idx == e) {
            int pos = c + __popc(m & ((1u << lane) - 1));
            if (pos < CAP_) { g_slot[e*CAP_ + pos] = base + lane; g_keep[base + lane] = 1; }
        }
        c += __popc(m);
    }
    if (lane == 0) g_ecnt[e] = (c < CAP_) ? c : CAP_;
    __syncthreads();
    for (int n = tid; n < NT_; n += 256) {
        float p0 = g_keep[2*n]   ? g_rawp[2*n]   : 0.f;
        float p1 = g_keep[2*n+1] ? g_rawp[2*n+1] : 0.f;
        float s = p0 + p1 + 1e-9f;
        float w0 = p0/s, w1 = p1/s;
        g_w[2*n] = w0; g_w[2*n+1] = w1;
        if (w0 > 0.f) atomicAdd(&g_eimp[g_topidx[2*n]],   w0);
        if (w1 > 0.f) atomicAdd(&g_eimp[g_topidx[2*n+1]], w1);
    }
}

// ---------------- FF GEMM 1: M=160 x N=128 (R14 tiles) -----------------------
__global__ void ff1_tc(const float* __restrict__ W1) {
    int e = blockIdx.z;
    int cnt = g_ecnt[e];
    int col0 = blockIdx.x*128;
    __shared__ int toks[192];
    __shared__ unsigned As[192][20];
    __shared__ unsigned Bs[16][132];
    int tid = threadIdx.x;
    if (tid < 192) toks[tid] = (tid < cnt) ? (g_slot[e*CAP_ + tid] >> 1) : -1;
    __syncthreads();
    const float* W = W1 + (size_t)e*D_*DFF_;
    int lane = tid & 31, wid = tid >> 5;
    int wm = (wid & 1)*80, wn = (wid >> 1)*32;
    int grp = lane >> 2, tig = lane & 3;
    int ar = tid >> 2, ac4 = (tid & 3)*4;
    int br = tid >> 5, bc4 = (tid & 31)*4;
    int tok[3];
    tok[0] = toks[ar]; tok[1] = toks[ar+64]; tok[2] = toks[ar+128];
    float acc[5][4][4];
    #pragma unroll
    for (int i = 0; i < 5; i++) for (int j = 0; j < 4; j++) for (int q = 0; q < 4; q++) acc[i][j][q] = 0.f;
    float4 aR[3], bR[2];
    float4 z4 = {0.f,0.f,0.f,0.f};
    #pragma unroll
    for (int rr = 0; rr < 3; rr++)
        aR[rr] = (tok[rr] >= 0) ? *(const float4*)&g_xn2[tok[rr]*D_ + ac4] : z4;
    #pragma unroll
    for (int rr = 0; rr < 2; rr++)
        bR[rr] = *(const float4*)&W[(size_t)(br+rr*8)*DFF_ + col0 + bc4];
    for (int k0 = 0; k0 < D_; k0 += 16) {
        #pragma unroll
        for (int rr = 0; rr < 3; rr++)
            st4(&As[ar+rr*64][ac4], aR[rr]);
        #pragma unroll
        for (int rr = 0; rr < 2; rr++)
            st4(&Bs[br+rr*8][bc4], bR[rr]);
        __syncthreads();
        if (k0 + 16 < D_) {
            #pragma unroll
            for (int rr = 0; rr < 3; rr++)
                aR[rr] = (tok[rr] >= 0) ? *(const float4*)&g_xn2[tok[rr]*D_ + k0+16 + ac4] : z4;
            #pragma unroll
            for (int rr = 0; rr < 2; rr++)
                bR[rr] = *(const float4*)&W[(size_t)(k0+16+br+rr*8)*DFF_ + col0 + bc4];
        }
        #pragma unroll
        for (int kk = 0; kk < 16; kk += 8) {
            unsigned a[5][4], b2[4][2];
            #pragma unroll
            for (int mi = 0; mi < 5; mi++) {
                int row = wm + mi*16 + grp, col = kk + tig;
                a[mi][0] = As[row][col];   a[mi][1] = As[row+8][col];
                a[mi][2] = As[row][col+4]; a[mi][3] = As[row+8][col+4];
            }
            #pragma unroll
            for (int nj = 0; nj < 4; nj++) {
                int bc = wn + nj*8 + grp;
                b2[nj][0] = Bs[kk+tig][bc]; b2[nj][1] = Bs[kk+4+tig][bc];
            }
            #pragma unroll
            for (int mi = 0; mi < 5; mi++)
                #pragma unroll
                for (int nj = 0; nj < 4; nj++) mma8(acc[mi][nj], a[mi], b2[nj]);
        }
        __syncthreads();
    }
    #pragma unroll
    for (int mi = 0; mi < 5; mi++)
        #pragma unroll
        for (int nj = 0; nj < 4; nj++) {
            int rl = wm + mi*16 + grp;
            int c = col0 + wn + nj*8 + tig*2;
            if (rl < cnt) {
                float* hp = &g_hmid[(size_t)(e*CAP_ + rl)*DFF_ + c];
                hp[0] = fmaxf(acc[mi][nj][0], 0.f);
                hp[1] = fmaxf(acc[mi][nj][1], 0.f);
            }
            if (rl + 8 < cnt) {
                float* hp = &g_hmid[(size_t)(e*CAP_ + rl + 8)*DFF_ + c];
                hp[0] = fmaxf(acc[mi][nj][2], 0.f);
                hp[1] = fmaxf(acc[mi][nj][3], 0.f);
            }
        }
}

// ---------------- FF GEMM 2: M=160 x N=128, K-split x3 (R14 tiles) -----------
__global__ void ff2_tc(const float* __restrict__ W2, float* __restrict__ out) {
    int e = blockIdx.z;
    int cnt = g_ecnt[e];
    int col0 = blockIdx.x*128;
    int kbase = blockIdx.y*(DFF_/3);
    __shared__ unsigned As[192][20];
    __shared__ unsigned Bs[16][132];
    int tid = threadIdx.x;
    const float* A = g_hmid + (size_t)e*CAP_*DFF_;
    const float* W = W2 + (size_t)e*DFF_*D_;
    int lane = tid & 31, wid = tid >> 5;
    int wm = (wid & 1)*80, wn = (wid >> 1)*32;
    int grp = lane >> 2, tig = lane & 3;
    int ar = tid >> 2, ac4 = (tid & 3)*4;
    int br = tid >> 5, bc4 = (tid & 31)*4;
    int ok[3];
    ok[0] = (ar < cnt); ok[1] = (ar + 64 < cnt); ok[2] = (ar + 128 < cnt);
    float acc[5][4][4];
    #pragma unroll
    for (int i = 0; i < 5; i++) for (int j = 0; j < 4; j++) for (int q = 0; q < 4; q++) acc[i][j][q] = 0.f;
    float4 aR[3], bR[2];
    float4 z4 = {0.f,0.f,0.f,0.f};
    #pragma unroll
    for (int rr = 0; rr < 3; rr++)
        aR[rr] = ok[rr] ? *(const float4*)&A[(size_t)(ar+rr*64)*DFF_ + kbase + ac4] : z4;
    #pragma unroll
    for (int rr = 0; rr < 2; rr++)
        bR[rr] = *(const float4*)&W[(size_t)(kbase+br+rr*8)*D_ + col0 + bc4];
    for (int k0 = kbase; k0 < kbase + DFF_/3; k0 += 16) {
        #pragma unroll
        for (int rr = 0; rr < 3; rr++)
            st4(&As[ar+rr*64][ac4], aR[rr]);
        #pragma unroll
        for (int rr = 0; rr < 2; rr++)
            st4(&Bs[br+rr*8][bc4], bR[rr]);
        __syncthreads();
        if (k0 + 16 < kbase + DFF_/3) {
            #pragma unroll
            for (int rr = 0; rr < 3; rr++)
                aR[rr] = ok[rr] ? *(const float4*)&A[(size_t)(ar+rr*64)*DFF_ + k0+16 + ac4] : z4;
            #pragma unroll
            for (int rr = 0; rr < 2; rr++)
                bR[rr] = *(const float4*)&W[(size_t)(k0+16+br+rr*8)*D_ + col0 + bc4];
        }
        #pragma unroll
        for (int kk = 0; kk < 16; kk += 8) {
            unsigned a[5][4], b2[4][2];
            #pragma unroll
            for (int mi = 0; mi < 5; mi++) {
                int row = wm + mi*16 + grp, col = kk + tig;
                a[mi][0] = As[row][col];   a[mi][1] = As[row+8][col];
                a[mi][2] = As[row][col+4]; a[mi][3] = As[row+8][col+4];
            }
            #pragma unroll
            for (int nj = 0; nj < 4; nj++) {
                int bc = wn + nj*8 + grp;
                b2[nj][0] = Bs[kk+tig][bc]; b2[nj][1] = Bs[kk+4+tig][bc];
            }
            #pragma unroll
            for (int mi = 0; mi < 5; mi++)
                #pragma unroll
                for (int nj = 0; nj < 4; nj++) mma8(acc[mi][nj], a[mi], b2[nj]);
        }
        __syncthreads();
    }
    #pragma unroll
    for (int mi = 0; mi < 5; mi++)
        #pragma unroll
        for (int nj = 0; nj < 4; nj++) {
            int rl = wm + mi*16 + grp;
            int c = col0 + wn + nj*8 + tig*2;
            if (rl < cnt) {
                int slot = g_slot[e*CAP_ + rl];
                int tok = slot >> 1;
                float w = g_w[slot];
                atomicAdd(&out[tok*D_ + c],   w*acc[mi][nj][0]);
                atomicAdd(&out[tok*D_ + c+1], w*acc[mi][nj][1]);
            }
            if (rl + 8 < cnt) {
                int slot = g_slot[e*CAP_ + rl + 8];
                int tok = slot >> 1;
                float w = g_w[slot];
                atomicAdd(&out[tok*D_ + c],   w*acc[mi][nj][2]);
                atomicAdd(&out[tok*D_ + c+1], w*acc[mi][nj][3]);
            }
        }
}

// ---------------- aux --------------------------------------------------------
__global__ void aux_kernel(float* __restrict__ out, int out_size) {
    if (blockIdx.x != 0 || threadIdx.x != 0) return;
    float ema[H_*EA_];
    float es = 0.f;
    for (int i = 0; i < H_*EA_; i++) { ema[i] = 0.01f*(float)g_headcnt[i]/(float)NT_; es += ema[i]; }
    float aux1 = 0.f;
    for (int i = 0; i < H_*EA_; i++) { float pr = ema[i]/(es + 1e-9f); aux1 += pr*pr; }
    aux1 *= (float)(EA_*H_);
    float sc = 0.f, si = 0.f;
    for (int e = 0; e < EF_; e++) { sc += (float)g_ecnt[e]; si += g_eimp[e]; }
    float aux2 = 0.f;
    for (int e = 0; e < EF_; e++)
        aux2 += ((float)g_ecnt[e]/(sc + 1e-9f)) * (g_eimp[e]/(si + 1e-9f));
    aux2 *= (float)EF_;
    float a = aux1 + aux2;
    for (int i = BSD_; i < out_size; i++) out[i] = a;
}

// ---------------- launch: fork/join DAG over two streams ---------------------
extern "C" void kernel_launch(void* const* d_in, const int* in_sizes, int n_in,
                              void* d_out, int out_size) {
    const float* x    = (const float*)d_in[0];
    const float* mask = (const float*)d_in[1];
    const float* ln1g = (const float*)d_in[2];
    const float* ln1b = (const float*)d_in[3];
    const float* ln2g = (const float*)d_in[4];
    const float* ln2b = (const float*)d_in[5];
    const float* Wq   = (const float*)d_in[6];
    const float* Wk   = (const float*)d_in[7];
    const float* Wv   = (const float*)d_in[8];
    const float* Wo   = (const float*)d_in[9];
    const float* rw   = (const float*)d_in[10];
    const float* gw   = (const float*)d_in[11];
    const float* W1   = (const float*)d_in[12];
    const float* W2   = (const float*)d_in[13];
    float* out = (float*)d_out;

    cudaStream_t s1;
    cudaEvent_t ev0, evA, evB, evC, evD;
    cudaStreamCreateWithFlags(&s1, cudaStreamNonBlocking);
    cudaEventCreateWithFlags(&ev0, cudaEventDisableTiming);
    cudaEventCreateWithFlags(&evA, cudaEventDisableTiming);
    cudaEventCreateWithFlags(&evB, cudaEventDisableTiming);
    cudaEventCreateWithFlags(&evC, cudaEventDisableTiming);
    cudaEventCreateWithFlags(&evD, cudaEventDisableTiming);

    // fork at entry: init runs on side stream under ln1
    cudaEventRecord(ev0, 0);
    cudaStreamWaitEvent(s1, ev0, 0);
    init_kernel<<<256, 256, 0, s1>>>();

    ln_kernel<<<NT_/8, 256>>>(x, ln1g, ln1b, 0);

    // side chain (router -> argmax -> vproj) under qk/scores/softmax
    cudaEventRecord(evA, 0);
    cudaStreamWaitEvent(s1, evA, 0);
    smalln_gemm<<<dim3(NT_/64, D_/64), 256, 0, s1>>>(rw, H_*EA_, 0);
    argmax_router<<<(NT_*H_ + 255)/256, 256, 0, s1>>>();
    vproj_kernel<<<dim3(NT_/4, H_), 256, 0, s1>>>(Wv);
    cudaEventRecord(evB, s1);

    qk_tc<<<dim3(D_/64, NT_/128, 2), 256>>>(Wq, Wk);
    scores_tc<<<dim3(S_/128, S_/128, B_*H_), 256>>>(mask);
    softmax_kernel<<<B_*H_*S_/8, 256>>>();

    cudaStreamWaitEvent(0, evB, 0);
    attn_tc<<<dim3(S_/128, 1, B_*H_), 256>>>();
    oproj_kernel<<<dim3(NT_/4, H_), 256>>>(x, Wo, out);
    ln_kernel<<<NT_/8, 256>>>(x, ln2g, ln2b, 1);
    smalln_gemm<<<dim3(NT_/64, D_/64), 256>>>(gw, EF_, 1);
    gate_dispatch_kernel<<<1, 256>>>();

    // aux overlaps ff1/ff2 (writes out[BSD..), disjoint from ff2's atomics)
    cudaEventRecord(evC, 0);
    cudaStreamWaitEvent(s1, evC, 0);
    aux_kernel<<<1, 32, 0, s1>>>(out, out_size);
    cudaEventRecord(evD, s1);

    ff1_tc<<<dim3(DFF_/128, 1, EF_), 256>>>(W1);
    ff2_tc<<<dim3(D_/128, 3, EF_), 256>>>(W2, out);
    cudaStreamWaitEvent(0, evD, 0);
}